// round 1
// baseline (speedup 1.0000x reference)
#include <cuda_runtime.h>
#include <cuda_bf16.h>
#include <math.h>

// Problem constants (fixed by the reference)
#define N1   100000
#define ND1  50000
#define E1   1600000
#define N2   50000
#define ND2  25000
#define E2   800000
#define BC   64          // B*C = 4*16 floats per node
#define NEG_SLOPE 0.01f

// ---------------- scratch (static device globals; no allocations) -----------
__device__ float g_Xt  [(size_t)N1  * BC];   // X transposed to [N,64]
__device__ float g_agg1[(size_t)ND1 * BC];
__device__ float g_deg1[ND1];
__device__ float g_h1  [(size_t)ND1 * BC];   // layer-1 output, [N,64] layout
__device__ float g_agg2[(size_t)ND2 * BC];
__device__ float g_deg2[ND2];

// ---------------- kernels ---------------------------------------------------

// X[b,n,c] (B=4,N,C=16) -> Xt[n, b*16+c], float4 granularity
__global__ void transpose_kernel(const float4* __restrict__ X,
                                 float4* __restrict__ Xt, int N)
{
    int g = blockIdx.x * blockDim.x + threadIdx.x;   // [0, N*16)
    if (g >= N * 16) return;
    int n  = g >> 4;
    int b  = (g >> 2) & 3;
    int c4 = g & 3;
    Xt[n * 16 + b * 4 + c4] = X[((size_t)b * N + n) * 4 + c4];
}

// One edge handled by 16 consecutive threads; each does one float4.
// gather Xt[src] * w, vectorized atomic scatter-add into agg[dst].
__global__ void edge_kernel(const float4* __restrict__ Xt,
                            const int*    __restrict__ src,
                            const int*    __restrict__ dst,
                            const float*  __restrict__ ew,
                            float4*       __restrict__ agg,
                            float*        __restrict__ deg,
                            int nE)
{
    int g = blockIdx.x * blockDim.x + threadIdx.x;
    int e = g >> 4;
    if (e >= nE) return;
    int lane = g & 15;
    int s = src[e];
    int d = dst[e];
    float w = ew[e];
    float4 v = Xt[(size_t)s * 16 + lane];
    v.x *= w; v.y *= w; v.z *= w; v.w *= w;
    atomicAdd(&agg[(size_t)d * 16 + lane], v);       // red.global.v4.f32 (sm_90+)
    if (lane == 0) atomicAdd(&deg[d], 1.0f);
}

// Per dst node: mean-normalize agg, concat with Xt[res], GEMM [4,32]@[32,16]+b,
// leaky_relu, write either [N,64] scratch or the final [B,ND,16] output.
// 64 threads per node, 4 nodes per 256-thread block.
template<bool FINAL>
__global__ void finalize_kernel(const float* __restrict__ Xsrc,   // [Nsrc,64]
                                const float* __restrict__ agg,    // [nD,64]
                                const float* __restrict__ deg,    // [nD]
                                const int*   __restrict__ res,    // [nD]
                                const float* __restrict__ W,      // [32,16]
                                const float* __restrict__ bias,   // [16]
                                float*       __restrict__ out,
                                int nD)
{
    __shared__ float sW[512];
    __shared__ float sB[16];
    __shared__ float sh[4][128];     // per node: [0..63]=x_res, [64..127]=mean agg

    int t = threadIdx.x;             // 256 threads
    sW[t]       = W[t];
    sW[t + 256] = W[t + 256];
    if (t < 16) sB[t] = bias[t];

    int local = t >> 6;              // node slot in block
    int tt    = t & 63;              // thread within node
    int n = blockIdx.x * 4 + local;

    if (n < nD) {
        int r = res[n];
        sh[local][tt] = Xsrc[(size_t)r * BC + tt];
        float invdeg = 1.0f / fmaxf(deg[n], 1.0f);
        sh[local][64 + tt] = agg[(size_t)n * BC + tt] * invdeg;
    }
    __syncthreads();
    if (n >= nD) return;

    int b = tt >> 4;
    int o = tt & 15;
    float acc = sB[o];
    #pragma unroll
    for (int k = 0; k < 16; k++)
        acc += sh[local][b * 16 + k] * sW[k * 16 + o];          // x_res part
    #pragma unroll
    for (int k = 0; k < 16; k++)
        acc += sh[local][64 + b * 16 + k] * sW[(16 + k) * 16 + o];  // agg part
    acc = (acc > 0.0f) ? acc : NEG_SLOPE * acc;

    if (FINAL)
        out[((size_t)b * nD + n) * 16 + o] = acc;   // [B, ND2, 16]
    else
        out[(size_t)n * BC + b * 16 + o] = acc;     // [N, 64] scratch
}

// ---------------- launch -----------------------------------------------------

extern "C" void kernel_launch(void* const* d_in, const int* in_sizes, int n_in,
                              void* d_out, int out_size)
{
    const float* X    = (const float*)d_in[0];
    const float* W1   = (const float*)d_in[1];
    const float* b1   = (const float*)d_in[2];
    const float* W2   = (const float*)d_in[3];
    const float* b2   = (const float*)d_in[4];
    const float* ew1  = (const float*)d_in[5];
    const float* ew2  = (const float*)d_in[6];
    const int*   src1 = (const int*)d_in[7];
    const int*   dst1 = (const int*)d_in[8];
    const int*   src2 = (const int*)d_in[9];
    const int*   dst2 = (const int*)d_in[10];
    const int*   res1 = (const int*)d_in[11];
    const int*   res2 = (const int*)d_in[12];
    float* out = (float*)d_out;

    float *Xt, *agg1, *deg1, *h1, *agg2, *deg2;
    cudaGetSymbolAddress((void**)&Xt,   g_Xt);
    cudaGetSymbolAddress((void**)&agg1, g_agg1);
    cudaGetSymbolAddress((void**)&deg1, g_deg1);
    cudaGetSymbolAddress((void**)&h1,   g_h1);
    cudaGetSymbolAddress((void**)&agg2, g_agg2);
    cudaGetSymbolAddress((void**)&deg2, g_deg2);

    cudaMemsetAsync(agg1, 0, (size_t)ND1 * BC * sizeof(float));
    cudaMemsetAsync(deg1, 0, (size_t)ND1 * sizeof(float));
    cudaMemsetAsync(agg2, 0, (size_t)ND2 * BC * sizeof(float));
    cudaMemsetAsync(deg2, 0, (size_t)ND2 * sizeof(float));

    // layer 0: transpose X -> Xt
    {
        int threads = N1 * 16;
        transpose_kernel<<<(threads + 255) / 256, 256>>>((const float4*)X,
                                                         (float4*)Xt, N1);
    }
    // layer 1 edges
    {
        int threads = E1 * 16;
        edge_kernel<<<(threads + 255) / 256, 256>>>((const float4*)Xt,
                                                    src1, dst1, ew1,
                                                    (float4*)agg1, deg1, E1);
    }
    // layer 1 finalize -> h1
    finalize_kernel<false><<<(ND1 + 3) / 4, 256>>>(Xt, agg1, deg1, res1,
                                                   W1, b1, h1, ND1);
    // layer 2 edges (input = h1, N2 == ND1)
    {
        int threads = E2 * 16;
        edge_kernel<<<(threads + 255) / 256, 256>>>((const float4*)h1,
                                                    src2, dst2, ew2,
                                                    (float4*)agg2, deg2, E2);
    }
    // layer 2 finalize -> d_out [4, ND2, 16]
    finalize_kernel<true><<<(ND2 + 3) / 4, 256>>>(h1, agg2, deg2, res2,
                                                  W2, b2, out, ND2);
}

// round 2
// speedup vs baseline: 1.1912x; 1.1912x over previous
#include <cuda_runtime.h>
#include <cuda_bf16.h>
#include <math.h>

// Problem constants (fixed by the reference)
#define N1   100000
#define ND1  50000
#define E1   1600000
#define N2   50000
#define ND2  25000
#define E2   800000
#define BC   64          // B*C = 4*16 floats per node
#define NEG_SLOPE 0.01f
#define EPW  8           // edges per warp in edge kernel

// ---------------- scratch (static device globals; no allocations) -----------
__device__ float g_Xt  [(size_t)N1  * BC];   // X transposed to [N,64]
__device__ float g_agg1[(size_t)ND1 * BC];
__device__ float g_deg1[ND1];
__device__ float g_h1  [(size_t)ND1 * BC];   // layer-1 output, [N,64] layout
__device__ float g_agg2[(size_t)ND2 * BC];
__device__ float g_deg2[ND2];

// ---------------- kernels ---------------------------------------------------

// Fused: X[b,n,c] -> Xt[n, b*16+c] transpose  +  zero all aggregation scratch.
__global__ void prep_kernel(const float4* __restrict__ X,
                            float4* __restrict__ Xt,
                            float4* __restrict__ agg1,
                            float4* __restrict__ agg2,
                            float*  __restrict__ deg1,
                            float*  __restrict__ deg2)
{
    int g = blockIdx.x * blockDim.x + threadIdx.x;   // [0, N1*16)
    if (g < N1 * 16) {
        int n  = g >> 4;
        int b  = (g >> 2) & 3;
        int c4 = g & 3;
        Xt[n * 16 + b * 4 + c4] = X[((size_t)b * N1 + n) * 4 + c4];
    }
    const float4 z = make_float4(0.f, 0.f, 0.f, 0.f);
    if (g < ND1 * 16) agg1[g] = z;
    if (g < ND2 * 16) agg2[g] = z;
    if (g < ND1)      deg1[g] = 0.f;
    if (g < ND2)      deg2[g] = 0.f;
}

// Warp-cooperative edge kernel: 8 edges per warp.
// Lanes 0-7 load src[eb..eb+7], lanes 8-15 dst, lanes 16-23 ew; shuffle-
// broadcast. Each thread handles one float4 lane of 4 edges -> 4 independent
// gathers in flight, then 4 vectorized atomic scatter-adds.
__global__ void edge_kernel(const float4* __restrict__ Xt,
                            const int*    __restrict__ src,
                            const int*    __restrict__ dst,
                            const float*  __restrict__ ew,
                            float4*       __restrict__ agg,
                            float*        __restrict__ deg,
                            int nE)
{
    int warp = (blockIdx.x * blockDim.x + threadIdx.x) >> 5;
    int lane = threadIdx.x & 31;
    int eb = warp * EPW;
    if (eb >= nE) return;

    // cooperative index/weight loads (3 coalesced 8-wide loads per warp)
    int   idxv = 0;
    float wv   = 0.f;
    int   li  = lane & 7;
    int   e_l = eb + li;
    bool  inb = e_l < nE;
    if (lane < 8)       { if (inb) idxv = src[e_l]; }
    else if (lane < 16) { if (inb) idxv = dst[e_l]; }
    else if (lane < 24) { if (inb) wv   = ew[e_l];  }

    int half = lane >> 4;      // which edge of the pair (0/1)
    int fl   = lane & 15;      // float4 index within the 64-float node block

    float4 v[4];
    int    didx[4];
    float  w[4];
    bool   act[4];

    #pragma unroll
    for (int u = 0; u < 4; u++) {
        int j  = 2 * u + half;                         // 0..7
        int s  = __shfl_sync(0xffffffffu, idxv, j);
        didx[u] = __shfl_sync(0xffffffffu, idxv, 8 + j);
        w[u]    = __shfl_sync(0xffffffffu, wv,   16 + j);
        act[u]  = (eb + j) < nE;
        if (!act[u]) s = 0;
        v[u] = Xt[(size_t)s * 16 + fl];                // 4 gathers in flight
    }

    #pragma unroll
    for (int u = 0; u < 4; u++) {
        if (!act[u]) continue;
        float ww = w[u];
        float4 t = v[u];
        t.x *= ww; t.y *= ww; t.z *= ww; t.w *= ww;
        atomicAdd(&agg[(size_t)didx[u] * 16 + fl], t); // red.global.v4.f32
        if (fl == 0) atomicAdd(&deg[didx[u]], 1.0f);
    }
}

// Per dst node: mean-normalize agg, concat with Xt[res], GEMM [4,32]@[32,16]+b,
// leaky_relu, write either [N,64] scratch or the final [B,ND,16] output.
// 64 threads per node, 4 nodes per 256-thread block.
template<bool FINAL>
__global__ void finalize_kernel(const float* __restrict__ Xsrc,   // [Nsrc,64]
                                const float* __restrict__ agg,    // [nD,64]
                                const float* __restrict__ deg,    // [nD]
                                const int*   __restrict__ res,    // [nD]
                                const float* __restrict__ W,      // [32,16]
                                const float* __restrict__ bias,   // [16]
                                float*       __restrict__ out,
                                int nD)
{
    __shared__ float sW[512];
    __shared__ float sB[16];
    __shared__ float sh[4][128];     // per node: [0..63]=x_res, [64..127]=mean agg

    int t = threadIdx.x;             // 256 threads
    sW[t]       = W[t];
    sW[t + 256] = W[t + 256];
    if (t < 16) sB[t] = bias[t];

    int local = t >> 6;              // node slot in block
    int tt    = t & 63;              // thread within node
    int n = blockIdx.x * 4 + local;

    if (n < nD) {
        int r = res[n];
        sh[local][tt] = Xsrc[(size_t)r * BC + tt];
        float invdeg = 1.0f / fmaxf(deg[n], 1.0f);
        sh[local][64 + tt] = agg[(size_t)n * BC + tt] * invdeg;
    }
    __syncthreads();
    if (n >= nD) return;

    int b = tt >> 4;
    int o = tt & 15;
    float acc = sB[o];
    #pragma unroll
    for (int k = 0; k < 16; k++)
        acc += sh[local][b * 16 + k] * sW[k * 16 + o];              // x_res part
    #pragma unroll
    for (int k = 0; k < 16; k++)
        acc += sh[local][64 + b * 16 + k] * sW[(16 + k) * 16 + o];  // agg part
    acc = (acc > 0.0f) ? acc : NEG_SLOPE * acc;

    if (FINAL)
        out[((size_t)b * nD + n) * 16 + o] = acc;   // [B, ND2, 16]
    else
        out[(size_t)n * BC + b * 16 + o] = acc;     // [N, 64] scratch
}

// ---------------- launch -----------------------------------------------------

extern "C" void kernel_launch(void* const* d_in, const int* in_sizes, int n_in,
                              void* d_out, int out_size)
{
    const float* X    = (const float*)d_in[0];
    const float* W1   = (const float*)d_in[1];
    const float* b1   = (const float*)d_in[2];
    const float* W2   = (const float*)d_in[3];
    const float* b2   = (const float*)d_in[4];
    const float* ew1  = (const float*)d_in[5];
    const float* ew2  = (const float*)d_in[6];
    const int*   src1 = (const int*)d_in[7];
    const int*   dst1 = (const int*)d_in[8];
    const int*   src2 = (const int*)d_in[9];
    const int*   dst2 = (const int*)d_in[10];
    const int*   res1 = (const int*)d_in[11];
    const int*   res2 = (const int*)d_in[12];
    float* out = (float*)d_out;

    float *Xt, *agg1, *deg1, *h1, *agg2, *deg2;
    cudaGetSymbolAddress((void**)&Xt,   g_Xt);
    cudaGetSymbolAddress((void**)&agg1, g_agg1);
    cudaGetSymbolAddress((void**)&deg1, g_deg1);
    cudaGetSymbolAddress((void**)&h1,   g_h1);
    cudaGetSymbolAddress((void**)&agg2, g_agg2);
    cudaGetSymbolAddress((void**)&deg2, g_deg2);

    // prep: transpose + zero scratch (one kernel, no memsets)
    {
        int threads = N1 * 16;       // covers all zeroing ranges too
        prep_kernel<<<(threads + 255) / 256, 256>>>((const float4*)X,
                                                    (float4*)Xt,
                                                    (float4*)agg1, (float4*)agg2,
                                                    deg1, deg2);
    }
    // layer 1 edges
    {
        int warps = (E1 + EPW - 1) / EPW;
        int threads = warps * 32;
        edge_kernel<<<(threads + 255) / 256, 256>>>((const float4*)Xt,
                                                    src1, dst1, ew1,
                                                    (float4*)agg1, deg1, E1);
    }
    // layer 1 finalize -> h1
    finalize_kernel<false><<<(ND1 + 3) / 4, 256>>>(Xt, agg1, deg1, res1,
                                                   W1, b1, h1, ND1);
    // layer 2 edges (input = h1, N2 == ND1)
    {
        int warps = (E2 + EPW - 1) / EPW;
        int threads = warps * 32;
        edge_kernel<<<(threads + 255) / 256, 256>>>((const float4*)h1,
                                                    src2, dst2, ew2,
                                                    (float4*)agg2, deg2, E2);
    }
    // layer 2 finalize -> d_out [4, ND2, 16]
    finalize_kernel<true><<<(ND2 + 3) / 4, 256>>>(h1, agg2, deg2, res2,
                                                  W2, b2, out, ND2);
}

// round 3
// speedup vs baseline: 1.2470x; 1.0469x over previous
#include <cuda_runtime.h>
#include <cuda_fp16.h>
#include <math.h>

// Problem constants (fixed by the reference)
#define N1   100000
#define ND1  50000
#define E1   1600000
#define N2   50000
#define ND2  25000
#define E2   800000
#define BC   64          // B*C = 4*16 values per node
#define NEG_SLOPE 0.01f
#define EPW  8           // edges per warp in edge kernel

// ---------------- scratch (static device globals; no allocations) -----------
__device__ __half g_Xt [(size_t)N1  * BC];   // fp16 node table, [N,64]
__device__ float  g_agg1[(size_t)ND1 * BC];
__device__ float  g_deg1[ND1];
__device__ __half g_h1 [(size_t)ND1 * BC];   // fp16 layer-1 output, [N,64]
__device__ float  g_agg2[(size_t)ND2 * BC];
__device__ float  g_deg2[ND2];

// ---------------- kernels ---------------------------------------------------

// Fused: X[b,n,c] (fp32) -> Xt[n, b*16+c] (fp16)  +  zero aggregation scratch.
// One thread per 4 values (half4 = uint2 store).
__global__ void prep_kernel(const float4* __restrict__ X,
                            uint2*  __restrict__ Xt,
                            float4* __restrict__ agg1,
                            float4* __restrict__ agg2,
                            float*  __restrict__ deg1,
                            float*  __restrict__ deg2)
{
    int g = blockIdx.x * blockDim.x + threadIdx.x;   // [0, N1*16)
    if (g < N1 * 16) {
        int n  = g >> 4;
        int b  = (g >> 2) & 3;
        int c4 = g & 3;
        float4 v = X[((size_t)b * N1 + n) * 4 + c4];
        __half2 lo = __floats2half2_rn(v.x, v.y);
        __half2 hi = __floats2half2_rn(v.z, v.w);
        uint2 packed;
        packed.x = *reinterpret_cast<unsigned*>(&lo);
        packed.y = *reinterpret_cast<unsigned*>(&hi);
        Xt[n * 16 + b * 4 + c4] = packed;
    }
    const float4 z = make_float4(0.f, 0.f, 0.f, 0.f);
    if (g < ND1 * 16) agg1[g] = z;
    if (g < ND2 * 16) agg2[g] = z;
    if (g < ND1)      deg1[g] = 0.f;
    if (g < ND2)      deg2[g] = 0.f;
}

// Warp-cooperative edge kernel: 8 edges per warp.
// Lanes 0-7 load src, 8-15 dst, 16-23 ew; shuffle-broadcast. Each thread does
// one half4 (8B) lane of 4 edges -> 4 independent gathers, then 4 vectorized
// fp32 atomic scatter-adds.
__global__ void edge_kernel(const uint2*  __restrict__ Xt,
                            const int*    __restrict__ src,
                            const int*    __restrict__ dst,
                            const float*  __restrict__ ew,
                            float4*       __restrict__ agg,
                            float*        __restrict__ deg,
                            int nE)
{
    int warp = (blockIdx.x * blockDim.x + threadIdx.x) >> 5;
    int lane = threadIdx.x & 31;
    int eb = warp * EPW;
    if (eb >= nE) return;

    // cooperative index/weight loads (3 coalesced 8-wide loads per warp)
    int   idxv = 0;
    float wv   = 0.f;
    int   li  = lane & 7;
    int   e_l = eb + li;
    bool  inb = e_l < nE;
    if (lane < 8)       { if (inb) idxv = src[e_l]; }
    else if (lane < 16) { if (inb) idxv = dst[e_l]; }
    else if (lane < 24) { if (inb) wv   = ew[e_l];  }

    int half_ = lane >> 4;     // which edge of the pair (0/1)
    int fl    = lane & 15;     // half4 index within the 64-half node block

    uint2 v[4];
    int   didx[4];
    float w[4];
    bool  act[4];

    #pragma unroll
    for (int u = 0; u < 4; u++) {
        int j   = 2 * u + half_;                       // 0..7
        int s   = __shfl_sync(0xffffffffu, idxv, j);
        didx[u] = __shfl_sync(0xffffffffu, idxv, 8 + j);
        w[u]    = __shfl_sync(0xffffffffu, wv,   16 + j);
        act[u]  = (eb + j) < nE;
        if (!act[u]) s = 0;
        v[u] = Xt[(size_t)s * 16 + fl];                // 4 x 8B gathers in flight
    }

    #pragma unroll
    for (int u = 0; u < 4; u++) {
        if (!act[u]) continue;
        float ww = w[u];
        __half2 h0 = *reinterpret_cast<__half2*>(&v[u].x);
        __half2 h1 = *reinterpret_cast<__half2*>(&v[u].y);
        float2 a = __half22float2(h0);
        float2 b = __half22float2(h1);
        float4 t = make_float4(a.x * ww, a.y * ww, b.x * ww, b.y * ww);
        atomicAdd(&agg[(size_t)didx[u] * 16 + fl], t); // red.global.v4.f32
        if (fl == 0) atomicAdd(&deg[didx[u]], 1.0f);
    }
}

// Per dst node: mean-normalize agg, concat with Xsrc[res] (fp16 table),
// GEMM [4,32]@[32,16]+b in fp32, leaky_relu, write fp16 scratch or fp32 out.
// 64 threads per node, 4 nodes per 256-thread block.
template<bool FINAL>
__global__ void finalize_kernel(const __half* __restrict__ Xsrc,  // [Nsrc,64] fp16
                                const float*  __restrict__ agg,   // [nD,64]
                                const float*  __restrict__ deg,   // [nD]
                                const int*    __restrict__ res,   // [nD]
                                const float*  __restrict__ W,     // [32,16]
                                const float*  __restrict__ bias,  // [16]
                                void*         __restrict__ out,
                                int nD)
{
    __shared__ float sW[512];
    __shared__ float sB[16];
    __shared__ float sh[4][128];     // per node: [0..63]=x_res, [64..127]=mean agg

    int t = threadIdx.x;             // 256 threads
    sW[t]       = W[t];
    sW[t + 256] = W[t + 256];
    if (t < 16) sB[t] = bias[t];

    int local = t >> 6;              // node slot in block
    int tt    = t & 63;              // thread within node
    int n = blockIdx.x * 4 + local;

    if (n < nD) {
        int r = res[n];
        sh[local][tt] = __half2float(Xsrc[(size_t)r * BC + tt]);
        float invdeg = 1.0f / fmaxf(deg[n], 1.0f);
        sh[local][64 + tt] = agg[(size_t)n * BC + tt] * invdeg;
    }
    __syncthreads();
    if (n >= nD) return;

    int b = tt >> 4;
    int o = tt & 15;
    float acc = sB[o];
    #pragma unroll
    for (int k = 0; k < 16; k++)
        acc += sh[local][b * 16 + k] * sW[k * 16 + o];              // x_res part
    #pragma unroll
    for (int k = 0; k < 16; k++)
        acc += sh[local][64 + b * 16 + k] * sW[(16 + k) * 16 + o];  // agg part
    acc = (acc > 0.0f) ? acc : NEG_SLOPE * acc;

    if (FINAL)
        ((float*)out)[((size_t)b * nD + n) * 16 + o] = acc;     // [B, ND2, 16] fp32
    else
        ((__half*)out)[(size_t)n * BC + b * 16 + o] = __float2half_rn(acc);
}

// ---------------- launch -----------------------------------------------------

extern "C" void kernel_launch(void* const* d_in, const int* in_sizes, int n_in,
                              void* d_out, int out_size)
{
    const float* X    = (const float*)d_in[0];
    const float* W1   = (const float*)d_in[1];
    const float* b1   = (const float*)d_in[2];
    const float* W2   = (const float*)d_in[3];
    const float* b2   = (const float*)d_in[4];
    const float* ew1  = (const float*)d_in[5];
    const float* ew2  = (const float*)d_in[6];
    const int*   src1 = (const int*)d_in[7];
    const int*   dst1 = (const int*)d_in[8];
    const int*   src2 = (const int*)d_in[9];
    const int*   dst2 = (const int*)d_in[10];
    const int*   res1 = (const int*)d_in[11];
    const int*   res2 = (const int*)d_in[12];
    float* out = (float*)d_out;

    __half *Xt, *h1;
    float *agg1, *deg1, *agg2, *deg2;
    cudaGetSymbolAddress((void**)&Xt,   g_Xt);
    cudaGetSymbolAddress((void**)&agg1, g_agg1);
    cudaGetSymbolAddress((void**)&deg1, g_deg1);
    cudaGetSymbolAddress((void**)&h1,   g_h1);
    cudaGetSymbolAddress((void**)&agg2, g_agg2);
    cudaGetSymbolAddress((void**)&deg2, g_deg2);

    // prep: transpose+convert + zero scratch (one kernel, no memsets)
    {
        int threads = N1 * 16;       // covers all zeroing ranges too
        prep_kernel<<<(threads + 255) / 256, 256>>>((const float4*)X,
                                                    (uint2*)Xt,
                                                    (float4*)agg1, (float4*)agg2,
                                                    deg1, deg2);
    }
    // layer 1 edges
    {
        int warps = (E1 + EPW - 1) / EPW;
        int threads = warps * 32;
        edge_kernel<<<(threads + 255) / 256, 256>>>((const uint2*)Xt,
                                                    src1, dst1, ew1,
                                                    (float4*)agg1, deg1, E1);
    }
    // layer 1 finalize -> h1 (fp16)
    finalize_kernel<false><<<(ND1 + 3) / 4, 256>>>(Xt, agg1, deg1, res1,
                                                   W1, b1, h1, ND1);
    // layer 2 edges (input = h1, N2 == ND1)
    {
        int warps = (E2 + EPW - 1) / EPW;
        int threads = warps * 32;
        edge_kernel<<<(threads + 255) / 256, 256>>>((const uint2*)h1,
                                                    src2, dst2, ew2,
                                                    (float4*)agg2, deg2, E2);
    }
    // layer 2 finalize -> d_out [4, ND2, 16] fp32
    finalize_kernel<true><<<(ND2 + 3) / 4, 256>>>(h1, agg2, deg2, res2,
                                                  W2, b2, out, ND2);
}